// round 7
// baseline (speedup 1.0000x reference)
#include <cuda_runtime.h>
#include <math.h>

#define NN 4096
#define MAXN 256
#define NGRAPH 64

// ---------------- scratch (device globals; no allocation) ----------------
__device__ float g_f[NN * 64];          // per-layer linear features (both heads)
__device__ float g_xbuf[2][NN * 64];    // layer outputs (ping-pong)
__device__ float g_h[NN * 192];         // concat(x1,x2,x3)
__device__ int   g_col[NN * MAXN];      // CSR columns (contiguous per row)
__device__ int   g_cnt[NN];             // row neighbor counts
__device__ float g_s1p[NN * 2];         // attention src scores, [row*2+head]
__device__ float g_s2p[NN * 2];         // attention dst scores, [row*2+head]

// ---------------- GEMM f = x@Wcat + b, with fused attention scores -------
// BM=32, BN=64, BK=32, 256 threads. W layout [2][in][32], b [2][32]=[64].
__device__ __forceinline__ void gemm_attn(
    const float* __restrict__ x, int in,
    const float* __restrict__ W, const float* __restrict__ b,
    const float* __restrict__ a1w, const float* __restrict__ a1b,
    const float* __restrict__ a2w, const float* __restrict__ a2b,
    int bid)
{
    __shared__ float As[32][33];   // [kk][row]
    __shared__ float Ws[32][64];   // [kk][col]
    int row0 = bid * 32;
    int t  = threadIdx.x;
    int tc = t & 15;               // col group: cols 4tc..4tc+3 (one head)
    int tr = t >> 4;               // row group: rows 2tr, 2tr+1
    int lr = t >> 3;               // load row 0..31
    int lc = t & 7;                // load k-group (float4)
    float acc[2][4] = {{0.f,0.f,0.f,0.f},{0.f,0.f,0.f,0.f}};

    for (int kb = 0; kb < in; kb += 32) {
        float4 xv = *(const float4*)&x[(size_t)(row0 + lr) * in + kb + 4 * lc];
        As[4*lc+0][lr] = xv.x; As[4*lc+1][lr] = xv.y;
        As[4*lc+2][lr] = xv.z; As[4*lc+3][lr] = xv.w;
#pragma unroll
        for (int j = 0; j < 2; j++) {
            int u  = t + j * 256;
            int kk = u >> 4, q = u & 15;
            int kh = q >> 3, h = (4 * q) & 31;
            float4 wv = *(const float4*)&W[((size_t)kh * in + kb + kk) * 32 + h];
            *(float4*)&Ws[kk][4 * q] = wv;
        }
        __syncthreads();
#pragma unroll
        for (int kk = 0; kk < 32; kk++) {
            float a0 = As[kk][2*tr], a1 = As[kk][2*tr+1];
            float4 wv = *(float4*)&Ws[kk][4*tc];
            acc[0][0] = fmaf(a0, wv.x, acc[0][0]);
            acc[0][1] = fmaf(a0, wv.y, acc[0][1]);
            acc[0][2] = fmaf(a0, wv.z, acc[0][2]);
            acc[0][3] = fmaf(a0, wv.w, acc[0][3]);
            acc[1][0] = fmaf(a1, wv.x, acc[1][0]);
            acc[1][1] = fmaf(a1, wv.y, acc[1][1]);
            acc[1][2] = fmaf(a1, wv.z, acc[1][2]);
            acc[1][3] = fmaf(a1, wv.w, acc[1][3]);
        }
        __syncthreads();
    }

    // epilogue: bias, store f (float4), fused attention score partials
    int col = 4 * tc;
    float b0 = b[col], b1 = b[col+1], b2 = b[col+2], b3 = b[col+3];
    float w10 = a1w[col], w11 = a1w[col+1], w12 = a1w[col+2], w13 = a1w[col+3];
    float w20 = a2w[col], w21 = a2w[col+1], w22 = a2w[col+2], w23 = a2w[col+3];
    float p1[2], p2[2];
#pragma unroll
    for (int r = 0; r < 2; r++) {
        float f0 = acc[r][0]+b0, f1 = acc[r][1]+b1, f2 = acc[r][2]+b2, f3 = acc[r][3]+b3;
        int row = row0 + 2*tr + r;
        float4 fv = {f0, f1, f2, f3};
        *(float4*)&g_f[(size_t)row * 64 + col] = fv;
        p1[r] = f0*w10 + f1*w11 + f2*w12 + f3*w13;
        p2[r] = f0*w20 + f1*w21 + f2*w22 + f3*w23;
    }
#pragma unroll
    for (int o = 4; o; o >>= 1) {
        p1[0] += __shfl_down_sync(0xffffffffu, p1[0], o, 8);
        p1[1] += __shfl_down_sync(0xffffffffu, p1[1], o, 8);
        p2[0] += __shfl_down_sync(0xffffffffu, p2[0], o, 8);
        p2[1] += __shfl_down_sync(0xffffffffu, p2[1], o, 8);
    }
    if ((tc & 7) == 0) {
        int k = tc >> 3;   // head
#pragma unroll
        for (int r = 0; r < 2; r++) {
            int row = row0 + 2*tr + r;
            g_s1p[row * 2 + k] = p1[r] + a1b[k];
            g_s2p[row * 2 + k] = p2[r] + a2b[k];
        }
    }
}

// ---------------- CSR build (warp per row; float4 ballot ordering) -------
__device__ __forceinline__ void csr_body(const float* __restrict__ adj, int wrow) {
    int lane = threadIdx.x & 31;
    const float4* row = (const float4*)(adj + (size_t)wrow * NN);
    int* mycol = g_col + (size_t)wrow * MAXN;
    int base = 0;
#pragma unroll 2
    for (int it = 0; it < 32; it++) {
        float4 v = row[it * 32 + lane];
        int c0 = it * 128 + 4 * lane;
        unsigned lm = (1u << lane) - 1u;
        unsigned m0 = __ballot_sync(0xffffffffu, v.x > 0.0f);
        if (v.x > 0.0f) { int p = base + __popc(m0 & lm); if (p < MAXN) mycol[p] = c0; }
        base += __popc(m0);
        unsigned m1 = __ballot_sync(0xffffffffu, v.y > 0.0f);
        if (v.y > 0.0f) { int p = base + __popc(m1 & lm); if (p < MAXN) mycol[p] = c0 + 1; }
        base += __popc(m1);
        unsigned m2 = __ballot_sync(0xffffffffu, v.z > 0.0f);
        if (v.z > 0.0f) { int p = base + __popc(m2 & lm); if (p < MAXN) mycol[p] = c0 + 2; }
        base += __popc(m2);
        unsigned m3 = __ballot_sync(0xffffffffu, v.w > 0.0f);
        if (v.w > 0.0f) { int p = base + __popc(m3 & lm); if (p < MAXN) mycol[p] = c0 + 3; }
        base += __popc(m3);
    }
    if (lane == 0) g_cnt[wrow] = base < MAXN ? base : MAXN;
}

// ---------------- fused: CSR build + layer-1 GEMM (overlap HBM & FMA) ----
__global__ void fused_csr_gemm1(
    const float* __restrict__ x, const float* __restrict__ adj,
    const float* __restrict__ W, const float* __restrict__ b,
    const float* __restrict__ a1w, const float* __restrict__ a1b,
    const float* __restrict__ a2w, const float* __restrict__ a2b)
{
    if (blockIdx.x < 128) {
        gemm_attn(x, 512, W, b, a1w, a1b, a2w, a2b, blockIdx.x);
    } else {
        int wrow = (blockIdx.x - 128) * 8 + (threadIdx.x >> 5);
        csr_body(adj, wrow);
    }
}

// ---------------- GEMM kernel for layers 2/3 -----------------------------
__global__ void gemm_k(int sel,
    const float* __restrict__ W, const float* __restrict__ b,
    const float* __restrict__ a1w, const float* __restrict__ a1b,
    const float* __restrict__ a2w, const float* __restrict__ a2b)
{
    gemm_attn(g_xbuf[sel], 64, W, b, a1w, a1b, a2w, a2b, blockIdx.x);
}

// ---------------- sparse softmax aggregation, 1 warp per row -------------
// Block 256 = 8 warps = 8 rows. Phase A: both heads' softmax in one pass
// (packed s2), weights pre-normalized. Stage float4{byte_off, w0, w1, 0}.
// Phase B: lane = (q=lane>>4 stream, fe=lane&15 16B slot); one LDG.128
// covers a full 256B feature row per neighbor; weight picked by fe>>3.
__global__ void __launch_bounds__(256) aggregate(int outsel, int hoff) {
    __shared__ float4 pairs[8][MAXN];
    int wid  = threadIdx.x >> 5;
    int lane = threadIdx.x & 31;
    int i = blockIdx.x * 8 + wid;

    int cnt = g_cnt[i];
    float2 s1 = *(const float2*)&g_s1p[i * 2];
    const float2* __restrict__ s2 = (const float2*)g_s2p;
    const int* __restrict__ mycol = g_col + (size_t)i * MAXN;

    // phase A: logits -> max -> exp -> sum (<=8 chunks of 32)
    int   jr[8]; float w0r[8], w1r[8];
    int nchunk = (cnt + 31) >> 5;
    float m0 = -1e30f, m1 = -1e30f;
    for (int c = 0; c < nchunk; c++) {
        int n = c * 32 + lane;
        int j = 0; float e0 = -1e30f, e1 = -1e30f;
        if (n < cnt) {
            j = mycol[n];
            float2 sv = s2[j];
            e0 = s1.x + sv.x; e0 = e0 > 0.f ? e0 : 0.01f * e0;
            e1 = s1.y + sv.y; e1 = e1 > 0.f ? e1 : 0.01f * e1;
        }
        jr[c] = j << 8;
        w0r[c] = e0; w1r[c] = e1;
        m0 = fmaxf(m0, e0); m1 = fmaxf(m1, e1);
    }
#pragma unroll
    for (int o = 16; o; o >>= 1) {
        m0 = fmaxf(m0, __shfl_xor_sync(0xffffffffu, m0, o));
        m1 = fmaxf(m1, __shfl_xor_sync(0xffffffffu, m1, o));
    }
    float sm0 = 0.f, sm1 = 0.f;
    for (int c = 0; c < nchunk; c++) {
        int n = c * 32 + lane;
        float w0 = (n < cnt) ? __expf(w0r[c] - m0) : 0.f;
        float w1 = (n < cnt) ? __expf(w1r[c] - m1) : 0.f;
        w0r[c] = w0; w1r[c] = w1;
        sm0 += w0; sm1 += w1;
    }
#pragma unroll
    for (int o = 16; o; o >>= 1) {
        sm0 += __shfl_xor_sync(0xffffffffu, sm0, o);
        sm1 += __shfl_xor_sync(0xffffffffu, sm1, o);
    }
    float inv0 = 1.0f / sm0, inv1 = 1.0f / sm1;

    // stage dense, pre-normalized pairs; pad to even with zero weight
    for (int c = 0; c < nchunk; c++) {
        int n = c * 32 + lane;
        if (n < cnt) {
            float4 p = {__int_as_float(jr[c]), w0r[c] * inv0, w1r[c] * inv1, 0.f};
            pairs[wid][n] = p;
        }
    }
    if (lane == 0 && (cnt & 1)) {
        float4 z = {0.f, 0.f, 0.f, 0.f};
        pairs[wid][cnt] = z;
    }
    __syncwarp();

    // phase B: 2 neighbors / warp-iteration, full 256B row per neighbor
    int cnt2 = (cnt + 1) & ~1;
    int q  = lane >> 4;                    // neighbor stream 0..1
    int fe = lane & 15;                    // 16B slot 0..15
    int k  = fe >> 3;                      // head
    const char* __restrict__ fb = (const char*)g_f + fe * 16;
    const float4* __restrict__ pw = pairs[wid];
    float4 acc = {0.f, 0.f, 0.f, 0.f};
#pragma unroll 2
    for (int n = q; n < cnt2; n += 2) {
        float4 p = pw[n];
        float w = k ? p.z : p.y;
        float4 fv = *(const float4*)(fb + __float_as_int(p.x));
        acc.x = fmaf(w, fv.x, acc.x);
        acc.y = fmaf(w, fv.y, acc.y);
        acc.z = fmaf(w, fv.z, acc.z);
        acc.w = fmaf(w, fv.w, acc.w);
    }
    acc.x += __shfl_xor_sync(0xffffffffu, acc.x, 16);
    acc.y += __shfl_xor_sync(0xffffffffu, acc.y, 16);
    acc.z += __shfl_xor_sync(0xffffffffu, acc.z, 16);
    acc.w += __shfl_xor_sync(0xffffffffu, acc.w, 16);
    if (q == 0) {
        float4 o4;
        o4.x = fmaxf(acc.x, 0.f);
        o4.y = fmaxf(acc.y, 0.f);
        o4.z = fmaxf(acc.z, 0.f);
        o4.w = fmaxf(acc.w, 0.f);
        *(float4*)&g_xbuf[outsel][(size_t)i * 64 + fe * 4] = o4;
        *(float4*)&g_h[(size_t)i * 192 + hoff + fe * 4] = o4;
    }
}

// ---------------- fused segment-mean pool + classifier head --------------
__global__ void pool_head(const int* __restrict__ batch,
                          const float* __restrict__ Wf, const float* __restrict__ bf,
                          float* __restrict__ out) {
    int g = blockIdx.x;   // 64
    int t = threadIdx.x;  // 192
    __shared__ float pooled[192];
    __shared__ int sst, sen;
    if (t == 0) {
        int lo = 0, hi = NN;
        while (lo < hi) { int mid = (lo + hi) >> 1; if (batch[mid] < g) lo = mid + 1; else hi = mid; }
        sst = lo;
        hi = NN;
        while (lo < hi) { int mid = (lo + hi) >> 1; if (batch[mid] < g + 1) lo = mid + 1; else hi = mid; }
        sen = lo;
    }
    __syncthreads();
    float s = 0.f;
    for (int r = sst; r < sen; r++) s += g_h[(size_t)r * 192 + t];
    float c = (float)(sen - sst);
    pooled[t] = s / fmaxf(c, 1.0f);
    __syncthreads();
    if (t < 32) {
        float logit = 0.f, v = -1e30f;
        if (t < 10) {
            float acc = bf[t];
            for (int c2 = 0; c2 < 192; c2++) acc = fmaf(pooled[c2], Wf[c2 * 10 + t], acc);
            logit = acc; v = acc;
        }
#pragma unroll
        for (int o = 16; o; o >>= 1) v = fmaxf(v, __shfl_xor_sync(0xffffffffu, v, o));
        float e = (t < 10) ? __expf(logit - v) : 0.f;
        float sm = e;
#pragma unroll
        for (int o = 16; o; o >>= 1) sm += __shfl_xor_sync(0xffffffffu, sm, o);
        if (t < 10) out[g * 10 + t] = e / sm;
    }
}

// ---------------- launch --------------------------------------------------
extern "C" void kernel_launch(void* const* d_in, const int* in_sizes, int n_in,
                              void* d_out, int out_size) {
    const float* x     = (const float*)d_in[0];
    const float* adj   = (const float*)d_in[1];
    const int*   batch = (const int*)d_in[2];
    const float* W[3]   = {(const float*)d_in[3],  (const float*)d_in[9],  (const float*)d_in[15]};
    const float* b[3]   = {(const float*)d_in[4],  (const float*)d_in[10], (const float*)d_in[16]};
    const float* a1w[3] = {(const float*)d_in[5],  (const float*)d_in[11], (const float*)d_in[17]};
    const float* a1b[3] = {(const float*)d_in[6],  (const float*)d_in[12], (const float*)d_in[18]};
    const float* a2w[3] = {(const float*)d_in[7],  (const float*)d_in[13], (const float*)d_in[19]};
    const float* a2b[3] = {(const float*)d_in[8],  (const float*)d_in[14], (const float*)d_in[20]};
    const float* Wf = (const float*)d_in[21];
    const float* bf = (const float*)d_in[22];
    float* out = (float*)d_out;

    // layer 1 GEMM (blocks 0-127) overlapped with CSR build (blocks 128-639)
    fused_csr_gemm1<<<640, 256>>>(x, adj, W[0], b[0], a1w[0], a1b[0], a2w[0], a2b[0]);
    aggregate<<<NN / 8, 256>>>(0, 0);

    gemm_k<<<128, 256>>>(0, W[1], b[1], a1w[1], a1b[1], a2w[1], a2b[1]);
    aggregate<<<NN / 8, 256>>>(1, 64);

    gemm_k<<<128, 256>>>(1, W[2], b[2], a1w[2], a1b[2], a2w[2], a2b[2]);
    aggregate<<<NN / 8, 256>>>(0, 128);

    pool_head<<<NGRAPH, 192>>>(batch, Wf, bf, out);
}

// round 8
// speedup vs baseline: 1.0330x; 1.0330x over previous
#include <cuda_runtime.h>
#include <math.h>

#define NN 4096
#define MAXN 256
#define NGRAPH 64

// ---------------- scratch (device globals; no allocation) ----------------
__device__ float g_f[NN * 64];          // per-layer linear features (both heads)
__device__ float g_xbuf[2][NN * 64];    // layer outputs (ping-pong)
__device__ float g_h[NN * 192];         // concat(x1,x2,x3)
__device__ int   g_col[NN * MAXN];      // CSR columns (contiguous per row)
__device__ int   g_cnt[NN];             // row neighbor counts
__device__ float g_s1p[NN * 2];         // attention src scores, [row*2+head]
__device__ float g_s2p[NN * 2];         // attention dst scores, [row*2+head]

// ---------------- GEMM f = x@Wcat + b, with fused attention scores -------
// BM=32, BN=64, BK=32, 256 threads. W layout [2][in][32], b [2][32]=[64].
__device__ __forceinline__ void gemm_attn(
    const float* __restrict__ x, int in,
    const float* __restrict__ W, const float* __restrict__ b,
    const float* __restrict__ a1w, const float* __restrict__ a1b,
    const float* __restrict__ a2w, const float* __restrict__ a2b,
    int bid)
{
    __shared__ float As[32][33];   // [kk][row]
    __shared__ float Ws[32][64];   // [kk][col]
    int row0 = bid * 32;
    int t  = threadIdx.x;
    int tc = t & 15;               // col group: cols 4tc..4tc+3 (one head)
    int tr = t >> 4;               // row group: rows 2tr, 2tr+1
    int lr = t >> 3;               // load row 0..31
    int lc = t & 7;                // load k-group (float4)
    float acc[2][4] = {{0.f,0.f,0.f,0.f},{0.f,0.f,0.f,0.f}};

    for (int kb = 0; kb < in; kb += 32) {
        float4 xv = *(const float4*)&x[(size_t)(row0 + lr) * in + kb + 4 * lc];
        As[4*lc+0][lr] = xv.x; As[4*lc+1][lr] = xv.y;
        As[4*lc+2][lr] = xv.z; As[4*lc+3][lr] = xv.w;
#pragma unroll
        for (int j = 0; j < 2; j++) {
            int u  = t + j * 256;
            int kk = u >> 4, q = u & 15;
            int kh = q >> 3, h = (4 * q) & 31;
            float4 wv = *(const float4*)&W[((size_t)kh * in + kb + kk) * 32 + h];
            *(float4*)&Ws[kk][4 * q] = wv;
        }
        __syncthreads();
#pragma unroll
        for (int kk = 0; kk < 32; kk++) {
            float a0 = As[kk][2*tr], a1 = As[kk][2*tr+1];
            float4 wv = *(float4*)&Ws[kk][4*tc];
            acc[0][0] = fmaf(a0, wv.x, acc[0][0]);
            acc[0][1] = fmaf(a0, wv.y, acc[0][1]);
            acc[0][2] = fmaf(a0, wv.z, acc[0][2]);
            acc[0][3] = fmaf(a0, wv.w, acc[0][3]);
            acc[1][0] = fmaf(a1, wv.x, acc[1][0]);
            acc[1][1] = fmaf(a1, wv.y, acc[1][1]);
            acc[1][2] = fmaf(a1, wv.z, acc[1][2]);
            acc[1][3] = fmaf(a1, wv.w, acc[1][3]);
        }
        __syncthreads();
    }

    // epilogue: bias, store f (float4), fused attention score partials
    int col = 4 * tc;
    float b0 = b[col], b1 = b[col+1], b2 = b[col+2], b3 = b[col+3];
    float w10 = a1w[col], w11 = a1w[col+1], w12 = a1w[col+2], w13 = a1w[col+3];
    float w20 = a2w[col], w21 = a2w[col+1], w22 = a2w[col+2], w23 = a2w[col+3];
    float p1[2], p2[2];
#pragma unroll
    for (int r = 0; r < 2; r++) {
        float f0 = acc[r][0]+b0, f1 = acc[r][1]+b1, f2 = acc[r][2]+b2, f3 = acc[r][3]+b3;
        int row = row0 + 2*tr + r;
        float4 fv = {f0, f1, f2, f3};
        *(float4*)&g_f[(size_t)row * 64 + col] = fv;
        p1[r] = f0*w10 + f1*w11 + f2*w12 + f3*w13;
        p2[r] = f0*w20 + f1*w21 + f2*w22 + f3*w23;
    }
#pragma unroll
    for (int o = 4; o; o >>= 1) {
        p1[0] += __shfl_down_sync(0xffffffffu, p1[0], o, 8);
        p1[1] += __shfl_down_sync(0xffffffffu, p1[1], o, 8);
        p2[0] += __shfl_down_sync(0xffffffffu, p2[0], o, 8);
        p2[1] += __shfl_down_sync(0xffffffffu, p2[1], o, 8);
    }
    if ((tc & 7) == 0) {
        int k = tc >> 3;   // head
#pragma unroll
        for (int r = 0; r < 2; r++) {
            int row = row0 + 2*tr + r;
            g_s1p[row * 2 + k] = p1[r] + a1b[k];
            g_s2p[row * 2 + k] = p2[r] + a2b[k];
        }
    }
}

// ---------------- CSR build (warp per row; float4 ballot ordering) -------
__device__ __forceinline__ void csr_body(const float* __restrict__ adj, int wrow) {
    int lane = threadIdx.x & 31;
    const float4* row = (const float4*)(adj + (size_t)wrow * NN);
    int* mycol = g_col + (size_t)wrow * MAXN;
    int base = 0;
#pragma unroll 2
    for (int it = 0; it < 32; it++) {
        float4 v = row[it * 32 + lane];
        int c0 = it * 128 + 4 * lane;
        unsigned lm = (1u << lane) - 1u;
        unsigned m0 = __ballot_sync(0xffffffffu, v.x > 0.0f);
        if (v.x > 0.0f) { int p = base + __popc(m0 & lm); if (p < MAXN) mycol[p] = c0; }
        base += __popc(m0);
        unsigned m1 = __ballot_sync(0xffffffffu, v.y > 0.0f);
        if (v.y > 0.0f) { int p = base + __popc(m1 & lm); if (p < MAXN) mycol[p] = c0 + 1; }
        base += __popc(m1);
        unsigned m2 = __ballot_sync(0xffffffffu, v.z > 0.0f);
        if (v.z > 0.0f) { int p = base + __popc(m2 & lm); if (p < MAXN) mycol[p] = c0 + 2; }
        base += __popc(m2);
        unsigned m3 = __ballot_sync(0xffffffffu, v.w > 0.0f);
        if (v.w > 0.0f) { int p = base + __popc(m3 & lm); if (p < MAXN) mycol[p] = c0 + 3; }
        base += __popc(m3);
    }
    if (lane == 0) g_cnt[wrow] = base < MAXN ? base : MAXN;
}

// ---------------- fused: CSR build + layer-1 GEMM (overlap HBM & FMA) ----
__global__ void fused_csr_gemm1(
    const float* __restrict__ x, const float* __restrict__ adj,
    const float* __restrict__ W, const float* __restrict__ b,
    const float* __restrict__ a1w, const float* __restrict__ a1b,
    const float* __restrict__ a2w, const float* __restrict__ a2b)
{
    if (blockIdx.x < 128) {
        gemm_attn(x, 512, W, b, a1w, a1b, a2w, a2b, blockIdx.x);
    } else {
        int wrow = (blockIdx.x - 128) * 8 + (threadIdx.x >> 5);
        csr_body(adj, wrow);
    }
}

// ---------------- GEMM kernel for layers 2/3 -----------------------------
__global__ void gemm_k(int sel,
    const float* __restrict__ W, const float* __restrict__ b,
    const float* __restrict__ a1w, const float* __restrict__ a1b,
    const float* __restrict__ a2w, const float* __restrict__ a2b)
{
    gemm_attn(g_xbuf[sel], 64, W, b, a1w, a1b, a2w, a2b, blockIdx.x);
}

// ---------------- sparse softmax aggregation, 1 warp per row -------------
// Block 256 = 8 warps = 8 rows. Phase A: FULLY UNROLLED 8 predicated chunks
// (register-resident arrays — dynamic trip count would spill to local mem).
// Both heads in one pass; weights pre-normalized; staged as
// float4{byte_off, w0, w1, 0}. Phase B: lane = (q=lane>>4 stream, fe=lane&15
// 16B slot); one LDG.128 covers a full 256B feature row per neighbor.
__global__ void __launch_bounds__(256) aggregate(int outsel, int hoff) {
    __shared__ float4 pairs[8][MAXN];
    int wid  = threadIdx.x >> 5;
    int lane = threadIdx.x & 31;
    int i = blockIdx.x * 8 + wid;

    int cnt = g_cnt[i];
    float2 s1 = *(const float2*)&g_s1p[i * 2];
    const float2* __restrict__ s2 = (const float2*)g_s2p;
    const int* __restrict__ mycol = g_col + (size_t)i * MAXN;

    // phase A: logits -> max (8 fixed chunks, predicated)
    int   jr[8]; float w0r[8], w1r[8];
    float m0 = -1e30f, m1 = -1e30f;
#pragma unroll
    for (int c = 0; c < 8; c++) {
        int n = c * 32 + lane;
        bool v = n < cnt;
        int j = v ? mycol[n] : 0;
        float2 sv = s2[j];
        float e0 = s1.x + sv.x; e0 = e0 > 0.f ? e0 : 0.01f * e0;
        float e1 = s1.y + sv.y; e1 = e1 > 0.f ? e1 : 0.01f * e1;
        e0 = v ? e0 : -1e30f;
        e1 = v ? e1 : -1e30f;
        jr[c] = j << 8;
        w0r[c] = e0; w1r[c] = e1;
        m0 = fmaxf(m0, e0); m1 = fmaxf(m1, e1);
    }
#pragma unroll
    for (int o = 16; o; o >>= 1) {
        m0 = fmaxf(m0, __shfl_xor_sync(0xffffffffu, m0, o));
        m1 = fmaxf(m1, __shfl_xor_sync(0xffffffffu, m1, o));
    }
    // exp + sum (unrolled, predicated)
    float sm0 = 0.f, sm1 = 0.f;
#pragma unroll
    for (int c = 0; c < 8; c++) {
        int n = c * 32 + lane;
        bool v = n < cnt;
        float w0 = v ? __expf(w0r[c] - m0) : 0.f;
        float w1 = v ? __expf(w1r[c] - m1) : 0.f;
        w0r[c] = w0; w1r[c] = w1;
        sm0 += w0; sm1 += w1;
    }
#pragma unroll
    for (int o = 16; o; o >>= 1) {
        sm0 += __shfl_xor_sync(0xffffffffu, sm0, o);
        sm1 += __shfl_xor_sync(0xffffffffu, sm1, o);
    }
    float inv0 = 1.0f / sm0, inv1 = 1.0f / sm1;

    // stage dense, pre-normalized pairs (unrolled, predicated)
#pragma unroll
    for (int c = 0; c < 8; c++) {
        int n = c * 32 + lane;
        if (n < cnt) {
            float4 p = {__int_as_float(jr[c]), w0r[c] * inv0, w1r[c] * inv1, 0.f};
            pairs[wid][n] = p;
        }
    }
    if (lane == 0 && (cnt & 1)) {
        float4 z = {0.f, 0.f, 0.f, 0.f};
        pairs[wid][cnt] = z;
    }
    __syncwarp();

    // phase B: 2 neighbors / warp-iteration, full 256B row per neighbor
    int cnt2 = (cnt + 1) & ~1;
    int q  = lane >> 4;                    // neighbor stream 0..1
    int fe = lane & 15;                    // 16B slot 0..15
    int k  = fe >> 3;                      // head
    const char* __restrict__ fb = (const char*)g_f + fe * 16;
    const float4* __restrict__ pw = pairs[wid];
    float4 acc = {0.f, 0.f, 0.f, 0.f};
#pragma unroll 2
    for (int n = q; n < cnt2; n += 2) {
        float4 p = pw[n];
        float w = k ? p.z : p.y;
        float4 fv = *(const float4*)(fb + __float_as_int(p.x));
        acc.x = fmaf(w, fv.x, acc.x);
        acc.y = fmaf(w, fv.y, acc.y);
        acc.z = fmaf(w, fv.z, acc.z);
        acc.w = fmaf(w, fv.w, acc.w);
    }
    acc.x += __shfl_xor_sync(0xffffffffu, acc.x, 16);
    acc.y += __shfl_xor_sync(0xffffffffu, acc.y, 16);
    acc.z += __shfl_xor_sync(0xffffffffu, acc.z, 16);
    acc.w += __shfl_xor_sync(0xffffffffu, acc.w, 16);
    if (q == 0) {
        float4 o4;
        o4.x = fmaxf(acc.x, 0.f);
        o4.y = fmaxf(acc.y, 0.f);
        o4.z = fmaxf(acc.z, 0.f);
        o4.w = fmaxf(acc.w, 0.f);
        *(float4*)&g_xbuf[outsel][(size_t)i * 64 + fe * 4] = o4;
        *(float4*)&g_h[(size_t)i * 192 + hoff + fe * 4] = o4;
    }
}

// ---------------- fused segment-mean pool + classifier head --------------
__global__ void pool_head(const int* __restrict__ batch,
                          const float* __restrict__ Wf, const float* __restrict__ bf,
                          float* __restrict__ out) {
    int g = blockIdx.x;   // 64
    int t = threadIdx.x;  // 192
    __shared__ float pooled[192];
    __shared__ int sst, sen;
    if (t == 0) {
        int lo = 0, hi = NN;
        while (lo < hi) { int mid = (lo + hi) >> 1; if (batch[mid] < g) lo = mid + 1; else hi = mid; }
        sst = lo;
        hi = NN;
        while (lo < hi) { int mid = (lo + hi) >> 1; if (batch[mid] < g + 1) lo = mid + 1; else hi = mid; }
        sen = lo;
    }
    __syncthreads();
    float s = 0.f;
    for (int r = sst; r < sen; r++) s += g_h[(size_t)r * 192 + t];
    float c = (float)(sen - sst);
    pooled[t] = s / fmaxf(c, 1.0f);
    __syncthreads();
    if (t < 32) {
        float logit = 0.f, v = -1e30f;
        if (t < 10) {
            float acc = bf[t];
            for (int c2 = 0; c2 < 192; c2++) acc = fmaf(pooled[c2], Wf[c2 * 10 + t], acc);
            logit = acc; v = acc;
        }
#pragma unroll
        for (int o = 16; o; o >>= 1) v = fmaxf(v, __shfl_xor_sync(0xffffffffu, v, o));
        float e = (t < 10) ? __expf(logit - v) : 0.f;
        float sm = e;
#pragma unroll
        for (int o = 16; o; o >>= 1) sm += __shfl_xor_sync(0xffffffffu, sm, o);
        if (t < 10) out[g * 10 + t] = e / sm;
    }
}

// ---------------- launch --------------------------------------------------
extern "C" void kernel_launch(void* const* d_in, const int* in_sizes, int n_in,
                              void* d_out, int out_size) {
    const float* x     = (const float*)d_in[0];
    const float* adj   = (const float*)d_in[1];
    const int*   batch = (const int*)d_in[2];
    const float* W[3]   = {(const float*)d_in[3],  (const float*)d_in[9],  (const float*)d_in[15]};
    const float* b[3]   = {(const float*)d_in[4],  (const float*)d_in[10], (const float*)d_in[16]};
    const float* a1w[3] = {(const float*)d_in[5],  (const float*)d_in[11], (const float*)d_in[17]};
    const float* a1b[3] = {(const float*)d_in[6],  (const float*)d_in[12], (const float*)d_in[18]};
    const float* a2w[3] = {(const float*)d_in[7],  (const float*)d_in[13], (const float*)d_in[19]};
    const float* a2b[3] = {(const float*)d_in[8],  (const float*)d_in[14], (const float*)d_in[20]};
    const float* Wf = (const float*)d_in[21];
    const float* bf = (const float*)d_in[22];
    float* out = (float*)d_out;

    // layer 1 GEMM (blocks 0-127) overlapped with CSR build (blocks 128-639)
    fused_csr_gemm1<<<640, 256>>>(x, adj, W[0], b[0], a1w[0], a1b[0], a2w[0], a2b[0]);
    aggregate<<<NN / 8, 256>>>(0, 0);

    gemm_k<<<128, 256>>>(0, W[1], b[1], a1w[1], a1b[1], a2w[1], a2b[1]);
    aggregate<<<NN / 8, 256>>>(1, 64);

    gemm_k<<<128, 256>>>(1, W[2], b[2], a1w[2], a1b[2], a2w[2], a2b[2]);
    aggregate<<<NN / 8, 256>>>(0, 128);

    pool_head<<<NGRAPH, 192>>>(batch, Wf, bf, out);
}

// round 9
// speedup vs baseline: 1.4969x; 1.4490x over previous
#include <cuda_runtime.h>
#include <math.h>

#define NN 4096
#define MAXN 256
#define NGRAPH 64

// ---------------- scratch (device globals; no allocation) ----------------
__device__ float g_f[NN * 64];          // per-layer linear features (both heads)
__device__ float g_xbuf[2][NN * 64];    // layer outputs (ping-pong)
__device__ float g_h[NN * 192];         // concat(x1,x2,x3)
__device__ int   g_col[NN * MAXN];      // padded CSR columns
__device__ int   g_cnt[NN];             // row neighbor counts
__device__ float g_s1[2 * NN];          // attention src scores per head (k*NN+row)
__device__ float g_s2[2 * NN];          // attention dst scores per head

// ---------------- GEMM f = x@Wcat + b, with fused attention scores -------
// BM=32, BN=64, BK=32, 256 threads. W layout [2][in][32], b [2][32]=[64].
__device__ __forceinline__ void gemm_attn(
    const float* __restrict__ x, int in,
    const float* __restrict__ W, const float* __restrict__ b,
    const float* __restrict__ a1w, const float* __restrict__ a1b,
    const float* __restrict__ a2w, const float* __restrict__ a2b,
    int bid)
{
    __shared__ float As[32][33];   // [kk][row]
    __shared__ float Ws[32][64];   // [kk][col]
    int row0 = bid * 32;
    int t  = threadIdx.x;
    int tc = t & 15;               // col group: cols 4tc..4tc+3 (one head)
    int tr = t >> 4;               // row group: rows 2tr, 2tr+1
    int lr = t >> 3;               // load row 0..31
    int lc = t & 7;                // load k-group (float4)
    float acc[2][4] = {{0.f,0.f,0.f,0.f},{0.f,0.f,0.f,0.f}};

    for (int kb = 0; kb < in; kb += 32) {
        float4 xv = *(const float4*)&x[(size_t)(row0 + lr) * in + kb + 4 * lc];
        As[4*lc+0][lr] = xv.x; As[4*lc+1][lr] = xv.y;
        As[4*lc+2][lr] = xv.z; As[4*lc+3][lr] = xv.w;
#pragma unroll
        for (int j = 0; j < 2; j++) {
            int u  = t + j * 256;
            int kk = u >> 4, q = u & 15;
            int kh = q >> 3, h = (4 * q) & 31;
            float4 wv = *(const float4*)&W[((size_t)kh * in + kb + kk) * 32 + h];
            *(float4*)&Ws[kk][4 * q] = wv;
        }
        __syncthreads();
#pragma unroll
        for (int kk = 0; kk < 32; kk++) {
            float a0 = As[kk][2*tr], a1 = As[kk][2*tr+1];
            float4 wv = *(float4*)&Ws[kk][4*tc];
            acc[0][0] = fmaf(a0, wv.x, acc[0][0]);
            acc[0][1] = fmaf(a0, wv.y, acc[0][1]);
            acc[0][2] = fmaf(a0, wv.z, acc[0][2]);
            acc[0][3] = fmaf(a0, wv.w, acc[0][3]);
            acc[1][0] = fmaf(a1, wv.x, acc[1][0]);
            acc[1][1] = fmaf(a1, wv.y, acc[1][1]);
            acc[1][2] = fmaf(a1, wv.z, acc[1][2]);
            acc[1][3] = fmaf(a1, wv.w, acc[1][3]);
        }
        __syncthreads();
    }

    // epilogue: bias, store f (float4), fused attention score partials
    int col = 4 * tc;
    float b0 = b[col], b1 = b[col+1], b2 = b[col+2], b3 = b[col+3];
    float w10 = a1w[col], w11 = a1w[col+1], w12 = a1w[col+2], w13 = a1w[col+3];
    float w20 = a2w[col], w21 = a2w[col+1], w22 = a2w[col+2], w23 = a2w[col+3];
    float p1[2], p2[2];
#pragma unroll
    for (int r = 0; r < 2; r++) {
        float f0 = acc[r][0]+b0, f1 = acc[r][1]+b1, f2 = acc[r][2]+b2, f3 = acc[r][3]+b3;
        int row = row0 + 2*tr + r;
        float4 fv = {f0, f1, f2, f3};
        *(float4*)&g_f[(size_t)row * 64 + col] = fv;
        p1[r] = f0*w10 + f1*w11 + f2*w12 + f3*w13;
        p2[r] = f0*w20 + f1*w21 + f2*w22 + f3*w23;
    }
#pragma unroll
    for (int o = 4; o; o >>= 1) {
        p1[0] += __shfl_down_sync(0xffffffffu, p1[0], o, 8);
        p1[1] += __shfl_down_sync(0xffffffffu, p1[1], o, 8);
        p2[0] += __shfl_down_sync(0xffffffffu, p2[0], o, 8);
        p2[1] += __shfl_down_sync(0xffffffffu, p2[1], o, 8);
    }
    if ((tc & 7) == 0) {
        int k = tc >> 3;   // head
#pragma unroll
        for (int r = 0; r < 2; r++) {
            int row = row0 + 2*tr + r;
            g_s1[k * NN + row] = p1[r] + a1b[k];
            g_s2[k * NN + row] = p2[r] + a2b[k];
        }
    }
}

// ---------------- CSR build, software-pipelined (MLP=4) ------------------
// Warp per row; 8 macro-iterations each issue 4 independent LDG.128 before
// the dependent ballot chain. Compile-time indices only (no local spill).
__device__ __forceinline__ void csr_step(float4 v, int c0, int lane,
                                         int& base, int* __restrict__ mycol) {
    unsigned lm = (1u << lane) - 1u;
    unsigned m0 = __ballot_sync(0xffffffffu, v.x > 0.0f);
    if (v.x > 0.0f) { int p = base + __popc(m0 & lm); if (p < MAXN) mycol[p] = c0; }
    base += __popc(m0);
    unsigned m1 = __ballot_sync(0xffffffffu, v.y > 0.0f);
    if (v.y > 0.0f) { int p = base + __popc(m1 & lm); if (p < MAXN) mycol[p] = c0 + 1; }
    base += __popc(m1);
    unsigned m2 = __ballot_sync(0xffffffffu, v.z > 0.0f);
    if (v.z > 0.0f) { int p = base + __popc(m2 & lm); if (p < MAXN) mycol[p] = c0 + 2; }
    base += __popc(m2);
    unsigned m3 = __ballot_sync(0xffffffffu, v.w > 0.0f);
    if (v.w > 0.0f) { int p = base + __popc(m3 & lm); if (p < MAXN) mycol[p] = c0 + 3; }
    base += __popc(m3);
}

__device__ __forceinline__ void csr_body(const float* __restrict__ adj, int wrow) {
    int lane = threadIdx.x & 31;
    const float4* row = (const float4*)(adj + (size_t)wrow * NN);
    int* mycol = g_col + (size_t)wrow * MAXN;
    int base = 0;
#pragma unroll 1
    for (int mb = 0; mb < 8; mb++) {
        float4 v0 = row[(mb * 4 + 0) * 32 + lane];
        float4 v1 = row[(mb * 4 + 1) * 32 + lane];
        float4 v2 = row[(mb * 4 + 2) * 32 + lane];
        float4 v3 = row[(mb * 4 + 3) * 32 + lane];
        int c0 = mb * 512 + 4 * lane;
        csr_step(v0, c0,       lane, base, mycol);
        csr_step(v1, c0 + 128, lane, base, mycol);
        csr_step(v2, c0 + 256, lane, base, mycol);
        csr_step(v3, c0 + 384, lane, base, mycol);
    }
    if (lane == 0) g_cnt[wrow] = base < MAXN ? base : MAXN;
}

// ---------------- fused: CSR build + layer-1 GEMM (overlap HBM & FMA) ----
__global__ void fused_csr_gemm1(
    const float* __restrict__ x, const float* __restrict__ adj,
    const float* __restrict__ W, const float* __restrict__ b,
    const float* __restrict__ a1w, const float* __restrict__ a1b,
    const float* __restrict__ a2w, const float* __restrict__ a2b)
{
    if (blockIdx.x < 128) {
        gemm_attn(x, 512, W, b, a1w, a1b, a2w, a2b, blockIdx.x);
    } else {
        int wrow = (blockIdx.x - 128) * 8 + (threadIdx.x >> 5);
        csr_body(adj, wrow);
    }
}

// ---------------- GEMM kernel for layers 2/3 -----------------------------
__global__ void gemm_k(int sel,
    const float* __restrict__ W, const float* __restrict__ b,
    const float* __restrict__ a1w, const float* __restrict__ a1b,
    const float* __restrict__ a2w, const float* __restrict__ a2b)
{
    gemm_attn(g_xbuf[sel], 64, W, b, a1w, a1b, a2w, a2b, blockIdx.x);
}

// ---------------- sparse softmax aggregation, float4 gather --------------
// Block 256 = 8 warps = 4 rows x 2 heads. Warp layout: lane = (q, fe),
// q = lane>>3 (neighbor stream 0..3), fe = lane&7 (float4 feature slot).
// Per iteration a warp consumes 4 neighbors x 32 features via LDG.128.
__global__ void __launch_bounds__(256) aggregate(int outsel, int hoff) {
    __shared__ float2 pairs[8][MAXN];     // [warp][n] = {byte_off, w}
    int wid  = threadIdx.x >> 5;          // 0..7
    int lane = threadIdx.x & 31;
    int i = blockIdx.x * 4 + (wid >> 1);  // row
    int k = wid & 1;                      // head

    int cnt = g_cnt[i];
    float s1 = g_s1[k * NN + i];
    const float* __restrict__ s2 = g_s2 + k * NN;
    const int* __restrict__ mycol = g_col + (size_t)i * MAXN;

    // phase A: logits -> max -> exp -> sum (<=8 chunks of 32)
    int   jreg[8];
    float wreg[8];
    int nchunk = (cnt + 31) >> 5;
    float m = -1e30f;
    for (int c = 0; c < nchunk; c++) {
        int n = c * 32 + lane;
        int j = 0; float e = -1e30f;
        if (n < cnt) {
            j = mycol[n];
            e = s1 + s2[j];
            e = e > 0.f ? e : 0.01f * e;   // leaky_relu 0.01
        }
        jreg[c] = j; wreg[c] = e;
        m = fmaxf(m, e);
    }
#pragma unroll
    for (int o = 16; o; o >>= 1) m = fmaxf(m, __shfl_xor_sync(0xffffffffu, m, o));
    float s = 0.f;
    for (int c = 0; c < nchunk; c++) {
        int n = c * 32 + lane;
        float w = (n < cnt) ? __expf(wreg[c] - m) : 0.f;
        wreg[c] = w;
        s += w;
    }
#pragma unroll
    for (int o = 16; o; o >>= 1) s += __shfl_xor_sync(0xffffffffu, s, o);
    float inv = 1.0f / s;

    // stage packed pairs; head offset baked in; zero-weight padding to x4
    int cnt4 = (cnt + 3) & ~3;
    int kbase = k * 128;                   // byte offset of head half
    for (int c = 0; c < nchunk; c++) {
        int n = c * 32 + lane;
        if (n < cnt4) {
            float2 p;
            p.x = __int_as_float((jreg[c] << 8) + kbase);
            p.y = wreg[c];                 // 0 for padded slots
            pairs[wid][n] = p;
        }
    }
    __syncwarp();

    // phase B: 4 neighbors / iteration, LDG.128 per lane
    int q  = lane >> 3;                    // neighbor stream
    int fe = lane & 7;                     // float4 slot
    const char* __restrict__ fb = (const char*)g_f + fe * 16;
    const float2* __restrict__ pw = pairs[wid];
    float4 acc = {0.f, 0.f, 0.f, 0.f};
#pragma unroll 2
    for (int n = q; n < cnt4; n += 4) {
        float2 p = pw[n];
        float4 fv = *(const float4*)(fb + __float_as_int(p.x));
        acc.x = fmaf(p.y, fv.x, acc.x);
        acc.y = fmaf(p.y, fv.y, acc.y);
        acc.z = fmaf(p.y, fv.z, acc.z);
        acc.w = fmaf(p.y, fv.w, acc.w);
    }
    // reduce across the 4 neighbor streams (lanes differing in bits 3,4)
#pragma unroll
    for (int o = 8; o <= 16; o <<= 1) {
        acc.x += __shfl_xor_sync(0xffffffffu, acc.x, o);
        acc.y += __shfl_xor_sync(0xffffffffu, acc.y, o);
        acc.z += __shfl_xor_sync(0xffffffffu, acc.z, o);
        acc.w += __shfl_xor_sync(0xffffffffu, acc.w, o);
    }
    if (q == 0) {
        float4 o4;
        o4.x = fmaxf(acc.x * inv, 0.f);
        o4.y = fmaxf(acc.y * inv, 0.f);
        o4.z = fmaxf(acc.z * inv, 0.f);
        o4.w = fmaxf(acc.w * inv, 0.f);
        *(float4*)&g_xbuf[outsel][(size_t)i * 64 + k * 32 + fe * 4] = o4;
        *(float4*)&g_h[(size_t)i * 192 + hoff + k * 32 + fe * 4] = o4;
    }
}

// ---------------- fused segment-mean pool + classifier head --------------
__global__ void pool_head(const int* __restrict__ batch,
                          const float* __restrict__ Wf, const float* __restrict__ bf,
                          float* __restrict__ out) {
    int g = blockIdx.x;   // 64
    int t = threadIdx.x;  // 192
    __shared__ float pooled[192];
    __shared__ int sst, sen;
    if (t == 0) {
        int lo = 0, hi = NN;
        while (lo < hi) { int mid = (lo + hi) >> 1; if (batch[mid] < g) lo = mid + 1; else hi = mid; }
        sst = lo;
        hi = NN;
        while (lo < hi) { int mid = (lo + hi) >> 1; if (batch[mid] < g + 1) lo = mid + 1; else hi = mid; }
        sen = lo;
    }
    __syncthreads();
    float s = 0.f;
    for (int r = sst; r < sen; r++) s += g_h[(size_t)r * 192 + t];
    float c = (float)(sen - sst);
    pooled[t] = s / fmaxf(c, 1.0f);
    __syncthreads();
    if (t < 32) {
        float logit = 0.f, v = -1e30f;
        if (t < 10) {
            float acc = bf[t];
            for (int c2 = 0; c2 < 192; c2++) acc = fmaf(pooled[c2], Wf[c2 * 10 + t], acc);
            logit = acc; v = acc;
        }
#pragma unroll
        for (int o = 16; o; o >>= 1) v = fmaxf(v, __shfl_xor_sync(0xffffffffu, v, o));
        float e = (t < 10) ? __expf(logit - v) : 0.f;
        float sm = e;
#pragma unroll
        for (int o = 16; o; o >>= 1) sm += __shfl_xor_sync(0xffffffffu, sm, o);
        if (t < 10) out[g * 10 + t] = e / sm;
    }
}

// ---------------- launch --------------------------------------------------
extern "C" void kernel_launch(void* const* d_in, const int* in_sizes, int n_in,
                              void* d_out, int out_size) {
    const float* x     = (const float*)d_in[0];
    const float* adj   = (const float*)d_in[1];
    const int*   batch = (const int*)d_in[2];
    const float* W[3]   = {(const float*)d_in[3],  (const float*)d_in[9],  (const float*)d_in[15]};
    const float* b[3]   = {(const float*)d_in[4],  (const float*)d_in[10], (const float*)d_in[16]};
    const float* a1w[3] = {(const float*)d_in[5],  (const float*)d_in[11], (const float*)d_in[17]};
    const float* a1b[3] = {(const float*)d_in[6],  (const float*)d_in[12], (const float*)d_in[18]};
    const float* a2w[3] = {(const float*)d_in[7],  (const float*)d_in[13], (const float*)d_in[19]};
    const float* a2b[3] = {(const float*)d_in[8],  (const float*)d_in[14], (const float*)d_in[20]};
    const float* Wf = (const float*)d_in[21];
    const float* bf = (const float*)d_in[22];
    float* out = (float*)d_out;

    // layer 1 GEMM (blocks 0-127) overlapped with CSR build (blocks 128-639)
    fused_csr_gemm1<<<640, 256>>>(x, adj, W[0], b[0], a1w[0], a1b[0], a2w[0], a2b[0]);
    aggregate<<<NN / 4, 256>>>(0, 0);

    gemm_k<<<128, 256>>>(0, W[1], b[1], a1w[1], a1b[1], a2w[1], a2b[1]);
    aggregate<<<NN / 4, 256>>>(1, 64);

    gemm_k<<<128, 256>>>(1, W[2], b[2], a1w[2], a1b[2], a2w[2], a2b[2]);
    aggregate<<<NN / 4, 256>>>(0, 128);

    pool_head<<<NGRAPH, 192>>>(batch, Wf, bf, out);
}

// round 10
// speedup vs baseline: 1.5195x; 1.0151x over previous
#include <cuda_runtime.h>
#include <math.h>

#define NN 4096
#define MAXN 256
#define NGRAPH 64

// ---------------- scratch (device globals; no allocation) ----------------
__device__ float g_f[NN * 64];          // per-layer linear features (both heads)
__device__ float g_xbuf[2][NN * 64];    // layer outputs (ping-pong)
__device__ float g_h[NN * 192];         // concat(x1,x2,x3)
__device__ int   g_col[NN * MAXN];      // CSR columns (contiguous per row)
__device__ int   g_cnt[NN];             // row neighbor counts
__device__ float g_s1p[NN * 2];         // attention src scores [row*2+head]
__device__ float g_s2p[NN * 2];         // attention dst scores [row*2+head]

// ---------------- GEMM f = x@Wcat + b, with fused attention scores -------
// BM=32, BN=64, BK=32, 256 threads. W layout [2][in][32], b [2][32]=[64].
__device__ __forceinline__ void gemm_attn(
    const float* __restrict__ x, int in,
    const float* __restrict__ W, const float* __restrict__ b,
    const float* __restrict__ a1w, const float* __restrict__ a1b,
    const float* __restrict__ a2w, const float* __restrict__ a2b,
    int bid)
{
    __shared__ float As[32][33];   // [kk][row]
    __shared__ float Ws[32][64];   // [kk][col]
    int row0 = bid * 32;
    int t  = threadIdx.x;
    int tc = t & 15;               // col group: cols 4tc..4tc+3 (one head)
    int tr = t >> 4;               // row group: rows 2tr, 2tr+1
    int lr = t >> 3;               // load row 0..31
    int lc = t & 7;                // load k-group (float4)
    float acc[2][4] = {{0.f,0.f,0.f,0.f},{0.f,0.f,0.f,0.f}};

    for (int kb = 0; kb < in; kb += 32) {
        float4 xv = *(const float4*)&x[(size_t)(row0 + lr) * in + kb + 4 * lc];
        As[4*lc+0][lr] = xv.x; As[4*lc+1][lr] = xv.y;
        As[4*lc+2][lr] = xv.z; As[4*lc+3][lr] = xv.w;
#pragma unroll
        for (int j = 0; j < 2; j++) {
            int u  = t + j * 256;
            int kk = u >> 4, q = u & 15;
            int kh = q >> 3, h = (4 * q) & 31;
            float4 wv = *(const float4*)&W[((size_t)kh * in + kb + kk) * 32 + h];
            *(float4*)&Ws[kk][4 * q] = wv;
        }
        __syncthreads();
#pragma unroll
        for (int kk = 0; kk < 32; kk++) {
            float a0 = As[kk][2*tr], a1 = As[kk][2*tr+1];
            float4 wv = *(float4*)&Ws[kk][4*tc];
            acc[0][0] = fmaf(a0, wv.x, acc[0][0]);
            acc[0][1] = fmaf(a0, wv.y, acc[0][1]);
            acc[0][2] = fmaf(a0, wv.z, acc[0][2]);
            acc[0][3] = fmaf(a0, wv.w, acc[0][3]);
            acc[1][0] = fmaf(a1, wv.x, acc[1][0]);
            acc[1][1] = fmaf(a1, wv.y, acc[1][1]);
            acc[1][2] = fmaf(a1, wv.z, acc[1][2]);
            acc[1][3] = fmaf(a1, wv.w, acc[1][3]);
        }
        __syncthreads();
    }

    // epilogue: bias, store f (float4), fused attention score partials
    int col = 4 * tc;
    float b0 = b[col], b1 = b[col+1], b2 = b[col+2], b3 = b[col+3];
    float w10 = a1w[col], w11 = a1w[col+1], w12 = a1w[col+2], w13 = a1w[col+3];
    float w20 = a2w[col], w21 = a2w[col+1], w22 = a2w[col+2], w23 = a2w[col+3];
    float p1[2], p2[2];
#pragma unroll
    for (int r = 0; r < 2; r++) {
        float f0 = acc[r][0]+b0, f1 = acc[r][1]+b1, f2 = acc[r][2]+b2, f3 = acc[r][3]+b3;
        int row = row0 + 2*tr + r;
        float4 fv = {f0, f1, f2, f3};
        *(float4*)&g_f[(size_t)row * 64 + col] = fv;
        p1[r] = f0*w10 + f1*w11 + f2*w12 + f3*w13;
        p2[r] = f0*w20 + f1*w21 + f2*w22 + f3*w23;
    }
#pragma unroll
    for (int o = 4; o; o >>= 1) {
        p1[0] += __shfl_down_sync(0xffffffffu, p1[0], o, 8);
        p1[1] += __shfl_down_sync(0xffffffffu, p1[1], o, 8);
        p2[0] += __shfl_down_sync(0xffffffffu, p2[0], o, 8);
        p2[1] += __shfl_down_sync(0xffffffffu, p2[1], o, 8);
    }
    if ((tc & 7) == 0) {
        int k = tc >> 3;   // head
#pragma unroll
        for (int r = 0; r < 2; r++) {
            int row = row0 + 2*tr + r;
            g_s1p[row * 2 + k] = p1[r] + a1b[k];
            g_s2p[row * 2 + k] = p2[r] + a2b[k];
        }
    }
}

// ---------------- CSR build, software-pipelined (MLP=4) ------------------
__device__ __forceinline__ void csr_step(float4 v, int c0, int lane,
                                         int& base, int* __restrict__ mycol) {
    unsigned lm = (1u << lane) - 1u;
    unsigned m0 = __ballot_sync(0xffffffffu, v.x > 0.0f);
    if (v.x > 0.0f) { int p = base + __popc(m0 & lm); if (p < MAXN) mycol[p] = c0; }
    base += __popc(m0);
    unsigned m1 = __ballot_sync(0xffffffffu, v.y > 0.0f);
    if (v.y > 0.0f) { int p = base + __popc(m1 & lm); if (p < MAXN) mycol[p] = c0 + 1; }
    base += __popc(m1);
    unsigned m2 = __ballot_sync(0xffffffffu, v.z > 0.0f);
    if (v.z > 0.0f) { int p = base + __popc(m2 & lm); if (p < MAXN) mycol[p] = c0 + 2; }
    base += __popc(m2);
    unsigned m3 = __ballot_sync(0xffffffffu, v.w > 0.0f);
    if (v.w > 0.0f) { int p = base + __popc(m3 & lm); if (p < MAXN) mycol[p] = c0 + 3; }
    base += __popc(m3);
}

__device__ __forceinline__ void csr_body(const float* __restrict__ adj, int wrow) {
    int lane = threadIdx.x & 31;
    const float4* row = (const float4*)(adj + (size_t)wrow * NN);
    int* mycol = g_col + (size_t)wrow * MAXN;
    int base = 0;
#pragma unroll 1
    for (int mb = 0; mb < 8; mb++) {
        float4 v0 = row[(mb * 4 + 0) * 32 + lane];
        float4 v1 = row[(mb * 4 + 1) * 32 + lane];
        float4 v2 = row[(mb * 4 + 2) * 32 + lane];
        float4 v3 = row[(mb * 4 + 3) * 32 + lane];
        int c0 = mb * 512 + 4 * lane;
        csr_step(v0, c0,       lane, base, mycol);
        csr_step(v1, c0 + 128, lane, base, mycol);
        csr_step(v2, c0 + 256, lane, base, mycol);
        csr_step(v3, c0 + 384, lane, base, mycol);
    }
    if (lane == 0) g_cnt[wrow] = base < MAXN ? base : MAXN;
}

// ---------------- fused: CSR build + layer-1 GEMM (overlap HBM & FMA) ----
__global__ void fused_csr_gemm1(
    const float* __restrict__ x, const float* __restrict__ adj,
    const float* __restrict__ W, const float* __restrict__ b,
    const float* __restrict__ a1w, const float* __restrict__ a1b,
    const float* __restrict__ a2w, const float* __restrict__ a2b)
{
    if (blockIdx.x < 128) {
        gemm_attn(x, 512, W, b, a1w, a1b, a2w, a2b, blockIdx.x);
    } else {
        int wrow = (blockIdx.x - 128) * 8 + (threadIdx.x >> 5);
        csr_body(adj, wrow);
    }
}

// ---------------- GEMM kernel for layers 2/3 -----------------------------
__global__ void gemm_k(int sel,
    const float* __restrict__ W, const float* __restrict__ b,
    const float* __restrict__ a1w, const float* __restrict__ a1b,
    const float* __restrict__ a2w, const float* __restrict__ a2b)
{
    gemm_attn(g_xbuf[sel], 64, W, b, a1w, a1b, a2w, a2b, blockIdx.x);
}

// ---------------- sparse softmax aggregation, 1 warp per row -------------
// No register arrays (spill-proof): logits go straight to smem, exp pass
// rewrites them. Phase B: lane = (q=lane>>4 stream, fe=lane&15 16B slot);
// one LDG.128 per lane covers a full 256B feature row; head = fe>>3.
__global__ void __launch_bounds__(256) aggregate(int outsel, int hoff) {
    __shared__ float4 pairs[8][MAXN];     // [warp][n] = {off, w0, w1, 0}
    int wid  = threadIdx.x >> 5;
    int lane = threadIdx.x & 31;
    int i = blockIdx.x * 8 + wid;

    int cnt = g_cnt[i];
    float2 s1 = *(const float2*)&g_s1p[i * 2];
    const float2* __restrict__ s2 = (const float2*)g_s2p;
    const int* __restrict__ mycol = g_col + (size_t)i * MAXN;
    float4* __restrict__ pw = pairs[wid];

    // pass 1: raw leaky logits -> smem; track per-head max in scalars
    float m0 = -1e30f, m1 = -1e30f;
    for (int n = lane; n < cnt; n += 32) {
        int j = mycol[n];
        float2 sv = s2[j];
        float e0 = s1.x + sv.x; e0 = e0 > 0.f ? e0 : 0.01f * e0;
        float e1 = s1.y + sv.y; e1 = e1 > 0.f ? e1 : 0.01f * e1;
        float4 p = {__int_as_float(j << 8), e0, e1, 0.f};
        pw[n] = p;
        m0 = fmaxf(m0, e0); m1 = fmaxf(m1, e1);
    }
#pragma unroll
    for (int o = 16; o; o >>= 1) {
        m0 = fmaxf(m0, __shfl_xor_sync(0xffffffffu, m0, o));
        m1 = fmaxf(m1, __shfl_xor_sync(0xffffffffu, m1, o));
    }

    // pass 2: exp + sum, rewrite weights in smem
    float sm0 = 0.f, sm1 = 0.f;
    for (int n = lane; n < cnt; n += 32) {
        float4 p = pw[n];
        float w0 = __expf(p.y - m0);
        float w1 = __expf(p.z - m1);
        sm0 += w0; sm1 += w1;
        p.y = w0; p.z = w1;
        pw[n] = p;
    }
#pragma unroll
    for (int o = 16; o; o >>= 1) {
        sm0 += __shfl_xor_sync(0xffffffffu, sm0, o);
        sm1 += __shfl_xor_sync(0xffffffffu, sm1, o);
    }
    float inv0 = 1.0f / sm0, inv1 = 1.0f / sm1;

    // pad to multiple of 4 with zero-weight slots
    int cnt4 = (cnt + 3) & ~3;
    if (lane < cnt4 - cnt) {
        float4 z = {0.f, 0.f, 0.f, 0.f};
        pw[cnt + lane] = z;
    }
    __syncwarp();

    // phase B: 4 neighbors / warp-iteration (2 per stream, MLP=2/lane)
    int q  = lane >> 4;                    // neighbor stream 0..1
    int fe = lane & 15;                    // 16B slot 0..15
    int k  = fe >> 3;                      // head
    const char* __restrict__ fb = (const char*)g_f + fe * 16;
    float4 acc = {0.f, 0.f, 0.f, 0.f};
#pragma unroll 1
    for (int n = q; n < cnt4; n += 4) {
        float4 pA = pw[n];
        float4 pB = pw[n + 2];
        float4 fvA = *(const float4*)(fb + __float_as_int(pA.x));
        float4 fvB = *(const float4*)(fb + __float_as_int(pB.x));
        float wA = k ? pA.z : pA.y;
        float wB = k ? pB.z : pB.y;
        acc.x = fmaf(wA, fvA.x, acc.x);
        acc.y = fmaf(wA, fvA.y, acc.y);
        acc.z = fmaf(wA, fvA.z, acc.z);
        acc.w = fmaf(wA, fvA.w, acc.w);
        acc.x = fmaf(wB, fvB.x, acc.x);
        acc.y = fmaf(wB, fvB.y, acc.y);
        acc.z = fmaf(wB, fvB.z, acc.z);
        acc.w = fmaf(wB, fvB.w, acc.w);
    }
    acc.x += __shfl_xor_sync(0xffffffffu, acc.x, 16);
    acc.y += __shfl_xor_sync(0xffffffffu, acc.y, 16);
    acc.z += __shfl_xor_sync(0xffffffffu, acc.z, 16);
    acc.w += __shfl_xor_sync(0xffffffffu, acc.w, 16);
    if (q == 0) {
        float inv = k ? inv1 : inv0;
        float4 o4;
        o4.x = fmaxf(acc.x * inv, 0.f);
        o4.y = fmaxf(acc.y * inv, 0.f);
        o4.z = fmaxf(acc.z * inv, 0.f);
        o4.w = fmaxf(acc.w * inv, 0.f);
        *(float4*)&g_xbuf[outsel][(size_t)i * 64 + fe * 4] = o4;
        *(float4*)&g_h[(size_t)i * 192 + hoff + fe * 4] = o4;
    }
}

// ---------------- fused segment-mean pool + classifier head --------------
__global__ void pool_head(const int* __restrict__ batch,
                          const float* __restrict__ Wf, const float* __restrict__ bf,
                          float* __restrict__ out) {
    int g = blockIdx.x;   // 64
    int t = threadIdx.x;  // 192
    __shared__ float pooled[192];
    __shared__ int sst, sen;
    if (t == 0) {
        int lo = 0, hi = NN;
        while (lo < hi) { int mid = (lo + hi) >> 1; if (batch[mid] < g) lo = mid + 1; else hi = mid; }
        sst = lo;
        hi = NN;
        while (lo < hi) { int mid = (lo + hi) >> 1; if (batch[mid] < g + 1) lo = mid + 1; else hi = mid; }
        sen = lo;
    }
    __syncthreads();
    float s = 0.f;
    for (int r = sst; r < sen; r++) s += g_h[(size_t)r * 192 + t];
    float c = (float)(sen - sst);
    pooled[t] = s / fmaxf(c, 1.0f);
    __syncthreads();
    if (t < 32) {
        float logit = 0.f, v = -1e30f;
        if (t < 10) {
            float acc = bf[t];
            for (int c2 = 0; c2 < 192; c2++) acc = fmaf(pooled[c2], Wf[c2 * 10 + t], acc);
            logit = acc; v = acc;
        }
#pragma unroll
        for (int o = 16; o; o >>= 1) v = fmaxf(v, __shfl_xor_sync(0xffffffffu, v, o));
        float e = (t < 10) ? __expf(logit - v) : 0.f;
        float sm = e;
#pragma unroll
        for (int o = 16; o; o >>= 1) sm += __shfl_xor_sync(0xffffffffu, sm, o);
        if (t < 10) out[g * 10 + t] = e / sm;
    }
}

// ---------------- launch --------------------------------------------------
extern "C" void kernel_launch(void* const* d_in, const int* in_sizes, int n_in,
                              void* d_out, int out_size) {
    const float* x     = (const float*)d_in[0];
    const float* adj   = (const float*)d_in[1];
    const int*   batch = (const int*)d_in[2];
    const float* W[3]   = {(const float*)d_in[3],  (const float*)d_in[9],  (const float*)d_in[15]};
    const float* b[3]   = {(const float*)d_in[4],  (const float*)d_in[10], (const float*)d_in[16]};
    const float* a1w[3] = {(const float*)d_in[5],  (const float*)d_in[11], (const float*)d_in[17]};
    const float* a1b[3] = {(const float*)d_in[6],  (const float*)d_in[12], (const float*)d_in[18]};
    const float* a2w[3] = {(const float*)d_in[7],  (const float*)d_in[13], (const float*)d_in[19]};
    const float* a2b[3] = {(const float*)d_in[8],  (const float*)d_in[14], (const float*)d_in[20]};
    const float* Wf = (const float*)d_in[21];
    const float* bf = (const float*)d_in[22];
    float* out = (float*)d_out;

    // layer 1 GEMM (blocks 0-127) overlapped with CSR build (blocks 128-639)
    fused_csr_gemm1<<<640, 256>>>(x, adj, W[0], b[0], a1w[0], a1b[0], a2w[0], a2b[0]);
    aggregate<<<NN / 8, 256>>>(0, 0);

    gemm_k<<<128, 256>>>(0, W[1], b[1], a1w[1], a1b[1], a2w[1], a2b[1]);
    aggregate<<<NN / 8, 256>>>(1, 64);

    gemm_k<<<128, 256>>>(1, W[2], b[2], a1w[2], a1b[2], a2w[2], a2b[2]);
    aggregate<<<NN / 8, 256>>>(0, 128);

    pool_head<<<NGRAPH, 192>>>(batch, Wf, bf, out);
}

// round 14
// speedup vs baseline: 1.5580x; 1.0253x over previous
#include <cuda_runtime.h>
#include <math.h>

#define NN 4096
#define MAXN 256
#define NGRAPH 64

// ---------------- scratch (device globals; no allocation) ----------------
__device__ float g_f[NN * 64];          // per-layer linear features (both heads)
__device__ float g_xbuf[2][NN * 64];    // layer outputs (ping-pong)
__device__ float g_h[NN * 192];         // concat(x1,x2,x3)
__device__ int   g_col[NN * MAXN];      // CSR columns (contiguous per row)
__device__ int   g_cnt[NN];             // row neighbor counts
__device__ float g_s1p[NN * 2];         // attention src scores [row*2+head]
__device__ float g_s2p[NN * 2];         // attention dst scores [row*2+head]

// ---------------- GEMM f = x@Wcat + b, with fused attention scores -------
// BM=32, BN=64, BK=32, 256 threads. W layout [2][in][32], b [2][32]=[64].
__device__ __forceinline__ void gemm_attn(
    const float* __restrict__ x, int in,
    const float* __restrict__ W, const float* __restrict__ b,
    const float* __restrict__ a1w, const float* __restrict__ a1b,
    const float* __restrict__ a2w, const float* __restrict__ a2b,
    int bid)
{
    __shared__ float As[32][33];   // [kk][row]
    __shared__ float Ws[32][64];   // [kk][col]
    int row0 = bid * 32;
    int t  = threadIdx.x;
    int tc = t & 15;               // col group: cols 4tc..4tc+3 (one head)
    int tr = t >> 4;               // row group: rows 2tr, 2tr+1
    int lr = t >> 3;               // load row 0..31
    int lc = t & 7;                // load k-group (float4)
    float acc[2][4] = {{0.f,0.f,0.f,0.f},{0.f,0.f,0.f,0.f}};

    for (int kb = 0; kb < in; kb += 32) {
        float4 xv = *(const float4*)&x[(size_t)(row0 + lr) * in + kb + 4 * lc];
        As[4*lc+0][lr] = xv.x; As[4*lc+1][lr] = xv.y;
        As[4*lc+2][lr] = xv.z; As[4*lc+3][lr] = xv.w;
#pragma unroll
        for (int j = 0; j < 2; j++) {
            int u  = t + j * 256;
            int kk = u >> 4, q = u & 15;
            int kh = q >> 3, h = (4 * q) & 31;
            float4 wv = *(const float4*)&W[((size_t)kh * in + kb + kk) * 32 + h];
            *(float4*)&Ws[kk][4 * q] = wv;
        }
        __syncthreads();
#pragma unroll
        for (int kk = 0; kk < 32; kk++) {
            float a0 = As[kk][2*tr], a1 = As[kk][2*tr+1];
            float4 wv = *(float4*)&Ws[kk][4*tc];
            acc[0][0] = fmaf(a0, wv.x, acc[0][0]);
            acc[0][1] = fmaf(a0, wv.y, acc[0][1]);
            acc[0][2] = fmaf(a0, wv.z, acc[0][2]);
            acc[0][3] = fmaf(a0, wv.w, acc[0][3]);
            acc[1][0] = fmaf(a1, wv.x, acc[1][0]);
            acc[1][1] = fmaf(a1, wv.y, acc[1][1]);
            acc[1][2] = fmaf(a1, wv.z, acc[1][2]);
            acc[1][3] = fmaf(a1, wv.w, acc[1][3]);
        }
        __syncthreads();
    }

    // epilogue: bias, store f (float4), fused attention score partials
    int col = 4 * tc;
    float b0 = b[col], b1 = b[col+1], b2 = b[col+2], b3 = b[col+3];
    float w10 = a1w[col], w11 = a1w[col+1], w12 = a1w[col+2], w13 = a1w[col+3];
    float w20 = a2w[col], w21 = a2w[col+1], w22 = a2w[col+2], w23 = a2w[col+3];
    float p1[2], p2[2];
#pragma unroll
    for (int r = 0; r < 2; r++) {
        float f0 = acc[r][0]+b0, f1 = acc[r][1]+b1, f2 = acc[r][2]+b2, f3 = acc[r][3]+b3;
        int row = row0 + 2*tr + r;
        float4 fv = {f0, f1, f2, f3};
        *(float4*)&g_f[(size_t)row * 64 + col] = fv;
        p1[r] = f0*w10 + f1*w11 + f2*w12 + f3*w13;
        p2[r] = f0*w20 + f1*w21 + f2*w22 + f3*w23;
    }
#pragma unroll
    for (int o = 4; o; o >>= 1) {
        p1[0] += __shfl_down_sync(0xffffffffu, p1[0], o, 8);
        p1[1] += __shfl_down_sync(0xffffffffu, p1[1], o, 8);
        p2[0] += __shfl_down_sync(0xffffffffu, p2[0], o, 8);
        p2[1] += __shfl_down_sync(0xffffffffu, p2[1], o, 8);
    }
    if ((tc & 7) == 0) {
        int k = tc >> 3;   // head
#pragma unroll
        for (int r = 0; r < 2; r++) {
            int row = row0 + 2*tr + r;
            g_s1p[row * 2 + k] = p1[r] + a1b[k];
            g_s2p[row * 2 + k] = p2[r] + a2b[k];
        }
    }
}

// ---------------- CSR build, software-pipelined (MLP=4) ------------------
__device__ __forceinline__ void csr_step(float4 v, int c0, int lane,
                                         int& base, int* __restrict__ mycol) {
    unsigned lm = (1u << lane) - 1u;
    unsigned m0 = __ballot_sync(0xffffffffu, v.x > 0.0f);
    if (v.x > 0.0f) { int p = base + __popc(m0 & lm); if (p < MAXN) mycol[p] = c0; }
    base += __popc(m0);
    unsigned m1 = __ballot_sync(0xffffffffu, v.y > 0.0f);
    if (v.y > 0.0f) { int p = base + __popc(m1 & lm); if (p < MAXN) mycol[p] = c0 + 1; }
    base += __popc(m1);
    unsigned m2 = __ballot_sync(0xffffffffu, v.z > 0.0f);
    if (v.z > 0.0f) { int p = base + __popc(m2 & lm); if (p < MAXN) mycol[p] = c0 + 2; }
    base += __popc(m2);
    unsigned m3 = __ballot_sync(0xffffffffu, v.w > 0.0f);
    if (v.w > 0.0f) { int p = base + __popc(m3 & lm); if (p < MAXN) mycol[p] = c0 + 3; }
    base += __popc(m3);
}

__device__ __forceinline__ void csr_body(const float* __restrict__ adj, int wrow) {
    int lane = threadIdx.x & 31;
    const float4* row = (const float4*)(adj + (size_t)wrow * NN);
    int* mycol = g_col + (size_t)wrow * MAXN;
    int base = 0;
#pragma unroll 1
    for (int mb = 0; mb < 8; mb++) {
        float4 v0 = row[(mb * 4 + 0) * 32 + lane];
        float4 v1 = row[(mb * 4 + 1) * 32 + lane];
        float4 v2 = row[(mb * 4 + 2) * 32 + lane];
        float4 v3 = row[(mb * 4 + 3) * 32 + lane];
        int c0 = mb * 512 + 4 * lane;
        csr_step(v0, c0,       lane, base, mycol);
        csr_step(v1, c0 + 128, lane, base, mycol);
        csr_step(v2, c0 + 256, lane, base, mycol);
        csr_step(v3, c0 + 384, lane, base, mycol);
    }
    if (lane == 0) g_cnt[wrow] = base < MAXN ? base : MAXN;
}

// ---------------- fused: CSR build + layer-1 GEMM (overlap HBM & FMA) ----
__global__ void fused_csr_gemm1(
    const float* __restrict__ x, const float* __restrict__ adj,
    const float* __restrict__ W, const float* __restrict__ b,
    const float* __restrict__ a1w, const float* __restrict__ a1b,
    const float* __restrict__ a2w, const float* __restrict__ a2b)
{
    if (blockIdx.x < 128) {
        gemm_attn(x, 512, W, b, a1w, a1b, a2w, a2b, blockIdx.x);
    } else {
        int wrow = (blockIdx.x - 128) * 8 + (threadIdx.x >> 5);
        csr_body(adj, wrow);
    }
}

// ---------------- GEMM kernel for layers 2/3 -----------------------------
__global__ void gemm_k(int sel,
    const float* __restrict__ W, const float* __restrict__ b,
    const float* __restrict__ a1w, const float* __restrict__ a1b,
    const float* __restrict__ a2w, const float* __restrict__ a2b)
{
    gemm_attn(g_xbuf[sel], 64, W, b, a1w, a1b, a2w, a2b, blockIdx.x);
}

// ---------------- sparse softmax aggregation, 1 warp per row -------------
// Spill-proof: logits staged in smem, exp pass rewrites them. Phase B:
// lane = (q=lane>>4 stream, fe=lane&15 16B slot); one LDG.128 per lane
// covers a full 256B feature row; head = fe>>3. 8 neighbors/warp-iter
// (4 per stream, MLP=4 per lane) to cover L2 gather latency.
__global__ void __launch_bounds__(256) aggregate(int outsel, int hoff) {
    __shared__ float4 pairs[8][MAXN];     // [warp][n] = {off, w0, w1, 0}
    int wid  = threadIdx.x >> 5;
    int lane = threadIdx.x & 31;
    int i = blockIdx.x * 8 + wid;

    int cnt = g_cnt[i];
    float2 s1 = *(const float2*)&g_s1p[i * 2];
    const float2* __restrict__ s2 = (const float2*)g_s2p;
    const int* __restrict__ mycol = g_col + (size_t)i * MAXN;
    float4* __restrict__ pw = pairs[wid];

    // pass 1: raw leaky logits -> smem; track per-head max in scalars
    float m0 = -1e30f, m1 = -1e30f;
    for (int n = lane; n < cnt; n += 32) {
        int j = mycol[n];
        float2 sv = s2[j];
        float e0 = s1.x + sv.x; e0 = e0 > 0.f ? e0 : 0.01f * e0;
        float e1 = s1.y + sv.y; e1 = e1 > 0.f ? e1 : 0.01f * e1;
        float4 p = {__int_as_float(j << 8), e0, e1, 0.f};
        pw[n] = p;
        m0 = fmaxf(m0, e0); m1 = fmaxf(m1, e1);
    }
#pragma unroll
    for (int o = 16; o; o >>= 1) {
        m0 = fmaxf(m0, __shfl_xor_sync(0xffffffffu, m0, o));
        m1 = fmaxf(m1, __shfl_xor_sync(0xffffffffu, m1, o));
    }

    // pass 2: exp + sum, rewrite weights in smem
    float sm0 = 0.f, sm1 = 0.f;
    for (int n = lane; n < cnt; n += 32) {
        float4 p = pw[n];
        float w0 = __expf(p.y - m0);
        float w1 = __expf(p.z - m1);
        sm0 += w0; sm1 += w1;
        p.y = w0; p.z = w1;
        pw[n] = p;
    }
#pragma unroll
    for (int o = 16; o; o >>= 1) {
        sm0 += __shfl_xor_sync(0xffffffffu, sm0, o);
        sm1 += __shfl_xor_sync(0xffffffffu, sm1, o);
    }
    float inv0 = 1.0f / sm0, inv1 = 1.0f / sm1;

    // pad to multiple of 8 with zero-weight slots
    int cnt8 = (cnt + 7) & ~7;
    if (lane < cnt8 - cnt) {
        float4 z = {0.f, 0.f, 0.f, 0.f};
        pw[cnt + lane] = z;
    }
    __syncwarp();

    // phase B: 8 neighbors / warp-iteration (4 per stream, MLP=4/lane)
    int q  = lane >> 4;                    // neighbor stream 0..1
    int fe = lane & 15;                    // 16B slot 0..15
    int k  = fe >> 3;                      // head
    const char* __restrict__ fb = (const char*)g_f + fe * 16;
    float4 acc = {0.f, 0.f, 0.f, 0.f};
#pragma unroll 1
    for (int base = 0; base < cnt8; base += 8) {
        int n0 = base + q * 4;
        float4 p0 = pw[n0 + 0];
        float4 p1 = pw[n0 + 1];
        float4 p2 = pw[n0 + 2];
        float4 p3 = pw[n0 + 3];
        float4 f0 = *(const float4*)(fb + __float_as_int(p0.x));
        float4 f1 = *(const float4*)(fb + __float_as_int(p1.x));
        float4 f2 = *(const float4*)(fb + __float_as_int(p2.x));
        float4 f3 = *(const float4*)(fb + __float_as_int(p3.x));
        float w0 = k ? p0.z : p0.y;
        float w1 = k ? p1.z : p1.y;
        float w2 = k ? p2.z : p2.y;
        float w3 = k ? p3.z : p3.y;
        acc.x = fmaf(w0, f0.x, acc.x);
        acc.y = fmaf(w0, f0.y, acc.y);
        acc.z = fmaf(w0, f0.z, acc.z);
        acc.w = fmaf(w0, f0.w, acc.w);
        acc.x = fmaf(w1, f1.x, acc.x);
        acc.y = fmaf(w1, f1.y, acc.y);
        acc.z = fmaf(w1, f1.z, acc.z);
        acc.w = fmaf(w1, f1.w, acc.w);
        acc.x = fmaf(w2, f2.x, acc.x);
        acc.y = fmaf(w2, f2.y, acc.y);
        acc.z = fmaf(w2, f2.z, acc.z);
        acc.w = fmaf(w2, f2.w, acc.w);
        acc.x = fmaf(w3, f3.x, acc.x);
        acc.y = fmaf(w3, f3.y, acc.y);
        acc.z = fmaf(w3, f3.z, acc.z);
        acc.w = fmaf(w3, f3.w, acc.w);
    }
    acc.x += __shfl_xor_sync(0xffffffffu, acc.x, 16);
    acc.y += __shfl_xor_sync(0xffffffffu, acc.y, 16);
    acc.z += __shfl_xor_sync(0xffffffffu, acc.z, 16);
    acc.w += __shfl_xor_sync(0xffffffffu, acc.w, 16);
    if (q == 0) {
        float inv = k ? inv1 : inv0;
        float4 o4;
        o4.x = fmaxf(acc.x * inv, 0.f);
        o4.y = fmaxf(acc.y * inv, 0.f);
        o4.z = fmaxf(acc.z * inv, 0.f);
        o4.w = fmaxf(acc.w * inv, 0.f);
        *(float4*)&g_xbuf[outsel][(size_t)i * 64 + fe * 4] = o4;
        *(float4*)&g_h[(size_t)i * 192 + hoff + fe * 4] = o4;
    }
}

// ---------------- fused segment-mean pool + classifier head --------------
__global__ void pool_head(const int* __restrict__ batch,
                          const float* __restrict__ Wf, const float* __restrict__ bf,
                          float* __restrict__ out) {
    int g = blockIdx.x;   // 64
    int t = threadIdx.x;  // 192
    __shared__ float pooled[192];
    __shared__ int sst, sen;
    if (t == 0) {
        int lo = 0, hi = NN;
        while (lo < hi) { int mid = (lo + hi) >> 1; if (batch[mid] < g) lo = mid + 1; else hi = mid; }
        sst = lo;
        hi = NN;
        while (lo < hi) { int mid = (lo + hi) >> 1; if (batch[mid] < g + 1) lo = mid + 1; else hi = mid; }
        sen = lo;
    }
    __syncthreads();
    float s = 0.f;
    for (int r = sst; r < sen; r++) s += g_h[(size_t)r * 192 + t];
    float c = (float)(sen - sst);
    pooled[t] = s / fmaxf(c, 1.0f);
    __syncthreads();
    if (t < 32) {
        float logit = 0.f, v = -1e30f;
        if (t < 10) {
            float acc = bf[t];
            for (int c2 = 0; c2 < 192; c2++) acc = fmaf(pooled[c2], Wf[c2 * 10 + t], acc);
            logit = acc; v = acc;
        }
#pragma unroll
        for (int o = 16; o; o >>= 1) v = fmaxf(v, __shfl_xor_sync(0xffffffffu, v, o));
        float e = (t < 10) ? __expf(logit - v) : 0.f;
        float sm = e;
#pragma unroll
        for (int o = 16; o; o >>= 1) sm += __shfl_xor_sync(0xffffffffu, sm, o);
        if (t < 10) out[g * 10 + t] = e / sm;
    }
}

// ---------------- launch --------------------------------------------------
extern "C" void kernel_launch(void* const* d_in, const int* in_sizes, int n_in,
                              void* d_out, int out_size) {
    const float* x     = (const float*)d_in[0];
    const float* adj   = (const float*)d_in[1];
    const int*   batch = (const int*)d_in[2];
    const float* W[3]   = {(const float*)d_in[3],  (const float*)d_in[9],  (const float*)d_in[15]};
    const float* b[3]   = {(const float*)d_in[4],  (const float*)d_in[10], (const float*)d_in[16]};
    const float* a1w[3] = {(const float*)d_in[5],  (const float*)d_in[11], (const float*)d_in[17]};
    const float* a1b[3] = {(const float*)d_in[6],  (const float*)d_in[12], (const float*)d_in[18]};
    const float* a2w[3] = {(const float*)d_in[7],  (const float*)d_in[13], (const float*)d_in[19]};
    const float* a2b[3] = {(const float*)d_in[8],  (const float*)d_in[14], (const float*)d_in[20]};
    const float* Wf = (const float*)d_in[21];
    const float* bf = (const float*)d_in[22];
    float* out = (float*)d_out;

    // layer 1 GEMM (blocks 0-127) overlapped with CSR build (blocks 128-639)
    fused_csr_gemm1<<<640, 256>>>(x, adj, W[0], b[0], a1w[0], a1b[0], a2w[0], a2b[0]);
    aggregate<<<NN / 8, 256>>>(0, 0);

    gemm_k<<<128, 256>>>(0, W[1], b[1], a1w[1], a1b[1], a2w[1], a2b[1]);
    aggregate<<<NN / 8, 256>>>(1, 64);

    gemm_k<<<128, 256>>>(1, W[2], b[2], a1w[2], a1b[2], a2w[2], a2b[2]);
    aggregate<<<NN / 8, 256>>>(0, 128);

    pool_head<<<NGRAPH, 192>>>(batch, Wf, bf, out);
}